// round 16
// baseline (speedup 1.0000x reference)
#include <cuda_runtime.h>
#include <cuda_bf16.h>
#include <math.h>
#include <stdint.h>

// Problem constants
#define T_STEPS 256
#define BATCH   256
#define NH      1024
#define KIN     105
#define KPAD    112
#define RS      85
#define NRULE   20
#define NOUT    33
#define NOPAD   48
#define TBROWS  (T_STEPS*BATCH)   // 65536
#define BH      (BATCH*NH)        // 262144

// ---------------- scratch (static device allocations only) ----------------
__device__ float g_pre[(long long)TBROWS*NH];             // 256 MB
__device__ __nv_bfloat16 g_hhi_all[(long long)TBROWS*NH]; // 128 MB
__device__ __nv_bfloat16 g_hlo_all[(long long)TBROWS*NH]; // 128 MB
__device__ __nv_bfloat16 g_Whi[NH*NH];
__device__ __nv_bfloat16 g_Wlo[NH*NH];
__device__ __nv_bfloat16 g_xhi[(long long)TBROWS*KPAD];
__device__ __nv_bfloat16 g_xlo[(long long)TBROWS*KPAD];
__device__ __nv_bfloat16 g_Wchi[NH*KPAD];
__device__ __nv_bfloat16 g_Wclo[NH*KPAD];
__device__ __nv_bfloat16 g_wouthi[NOPAD*NH];
__device__ __nv_bfloat16 g_woutlo[NOPAD*NH];
// one barrier counter per m-row (8 chains), 128B apart
__device__ __align__(128) unsigned g_rowbar[8*32];

// ======================= helpers ===========================================
__device__ __forceinline__ uint32_t smem_u32(const void* p) {
    uint32_t a;
    asm("{ .reg .u64 t; cvta.to.shared.u64 t, %1; cvt.u32.u64 %0, t; }"
        : "=r"(a) : "l"(p));
    return a;
}
__device__ __forceinline__ void cp_async16(uint32_t dst, const void* src) {
    asm volatile("cp.async.cg.shared.global [%0], [%1], 16;"
                 :: "r"(dst), "l"(src) : "memory");
}
__device__ __forceinline__ void cp_commit() {
    asm volatile("cp.async.commit_group;" ::: "memory");
}
template<int N> __device__ __forceinline__ void cp_wait() {
    asm volatile("cp.async.wait_group %0;" :: "n"(N) : "memory");
}
__device__ __forceinline__ void ldmat4(uint32_t& r0, uint32_t& r1,
                                       uint32_t& r2, uint32_t& r3, uint32_t a) {
    asm volatile("ldmatrix.sync.aligned.m8n8.x4.shared.b16 {%0,%1,%2,%3}, [%4];"
                 : "=r"(r0), "=r"(r1), "=r"(r2), "=r"(r3) : "r"(a));
}
__device__ __forceinline__ void mma16816(float* c, const uint32_t* a,
                                         const uint32_t* b) {
    asm volatile(
        "mma.sync.aligned.m16n8k16.row.col.f32.bf16.bf16.f32 "
        "{%0,%1,%2,%3}, {%4,%5,%6,%7}, {%8,%9}, {%0,%1,%2,%3};"
        : "+f"(c[0]), "+f"(c[1]), "+f"(c[2]), "+f"(c[3])
        : "r"(a[0]), "r"(a[1]), "r"(a[2]), "r"(a[3]), "r"(b[0]), "r"(b[1]));
}
__device__ __forceinline__ void pair_bar(int kg) {
    asm volatile("bar.sync %0, 64;" :: "r"(1 + kg) : "memory");
}

// ======================= merged split/prep kernel ==========================
__global__ void kprepall(const float* __restrict__ x,
                         const float* __restrict__ Wsens,
                         const float* __restrict__ Wrule,
                         const float* __restrict__ Wout,
                         const float* __restrict__ Wrec)
{
    long long idx = (long long)blockIdx.x * 256 + threadIdx.x;

    {
        int row = (int)(idx / KPAD);
        int k   = (int)(idx - (long long)row*KPAD);
        float v = (k < KIN) ? x[(long long)row*KIN + k] : 0.f;
        __nv_bfloat16 hi = __float2bfloat16(v);
        g_xhi[idx] = hi;
        g_xlo[idx] = __float2bfloat16(v - __bfloat162float(hi));
    }
    if (idx < (long long)NH*NH) {
        float w = Wrec[idx];
        __nv_bfloat16 hi = __float2bfloat16(w);
        g_Whi[idx] = hi;
        g_Wlo[idx] = __float2bfloat16(w - __bfloat162float(hi));
    }
    if (idx < (long long)NH*KPAD) {
        int n = (int)(idx / KPAD);
        int k = (int)(idx - (long long)n*KPAD);
        float v = (k < RS) ? Wsens[n*RS + k]
                : (k < KIN) ? Wrule[n*NRULE + (k - RS)] : 0.f;
        __nv_bfloat16 hi = __float2bfloat16(v);
        g_Wchi[idx] = hi;
        g_Wclo[idx] = __float2bfloat16(v - __bfloat162float(hi));
    }
    if (idx < (long long)NOPAD*NH) {
        int o = (int)(idx / NH);
        int k = (int)(idx - (long long)o*NH);
        float v = (o < NOUT) ? Wout[o*NH + k] : 0.f;
        __nv_bfloat16 hi = __float2bfloat16(v);
        g_wouthi[idx] = hi;
        g_woutlo[idx] = __float2bfloat16(v - __bfloat162float(hi));
    }
    if (idx < 8*32) g_rowbar[idx] = 0;
}

// ======================= kernelA: pre-activations (HMMA) ===================
#define A_PITCH 240
#define A_XHI 0
#define A_XLO 30720
#define A_WCH 61440
#define A_WCL 76800
#define A_SMEM 92160

__global__ void __launch_bounds__(256) kernelA(const float* __restrict__ noise,
                                               const float* __restrict__ bsens,
                                               const float* __restrict__ brec)
{
    extern __shared__ __align__(128) char smraw[];
    const uint32_t sb = smem_u32(smraw);
    const int tid  = threadIdx.x;
    const int wid  = tid >> 5;
    const int lane = tid & 31;
    const int wm   = wid & 3;
    const int wn   = wid >> 2;
    const int m0   = blockIdx.y * 128;
    const int n0   = blockIdx.x * 64;

#pragma unroll
    for (int i = 0; i < 7; i++) {
        int v = i*256 + tid;
        int r = v / 14, ch = v - r*14;
        long long gsrc = (long long)(m0 + r)*KPAD + ch*8;
        cp_async16(sb + A_XHI + r*A_PITCH + ch*16, g_xhi + gsrc);
        cp_async16(sb + A_XLO + r*A_PITCH + ch*16, g_xlo + gsrc);
    }
#pragma unroll
    for (int i = 0; i < 4; i++) {
        int v = i*256 + tid;
        if (v < 896) {
            int r = v / 14, ch = v - r*14;
            long long gsrc = (long long)(n0 + r)*KPAD + ch*8;
            cp_async16(sb + A_WCH + r*A_PITCH + ch*16, g_Wchi + gsrc);
            cp_async16(sb + A_WCL + r*A_PITCH + ch*16, g_Wclo + gsrc);
        }
    }
    cp_commit();
    cp_wait<0>();
    __syncthreads();

    const int aKoff = ((lane >> 4) & 1) * 16;
    const int bRow  = wn*32 + ((lane >> 4) & 1)*8 + (lane & 7);
    const int bKoff = ((lane >> 3) & 1) * 16;

    float acc[2][4][4];
#pragma unroll
    for (int a = 0; a < 2; a++)
#pragma unroll
        for (int b = 0; b < 4; b++)
#pragma unroll
            for (int e = 0; e < 4; e++) acc[a][b][e] = 0.f;

#pragma unroll
    for (int k = 0; k < 7; k++) {
        uint32_t ah[2][4], al[2][4], bh[8], bl[8];
#pragma unroll
        for (int mi = 0; mi < 2; mi++) {
            uint32_t ar = (wm*32 + mi*16 + (lane & 15))*A_PITCH + k*32 + aKoff;
            ldmat4(ah[mi][0], ah[mi][1], ah[mi][2], ah[mi][3], sb + A_XHI + ar);
            ldmat4(al[mi][0], al[mi][1], al[mi][2], al[mi][3], sb + A_XLO + ar);
        }
        uint32_t br0 = bRow*A_PITCH + k*32 + bKoff;
        uint32_t br1 = (bRow + 16)*A_PITCH + k*32 + bKoff;
        ldmat4(bh[0], bh[1], bh[2], bh[3], sb + A_WCH + br0);
        ldmat4(bh[4], bh[5], bh[6], bh[7], sb + A_WCH + br1);
        ldmat4(bl[0], bl[1], bl[2], bl[3], sb + A_WCL + br0);
        ldmat4(bl[4], bl[5], bl[6], bl[7], sb + A_WCL + br1);
#pragma unroll
        for (int mi = 0; mi < 2; mi++)
#pragma unroll
            for (int ni = 0; ni < 4; ni++) {
                mma16816(acc[mi][ni], ah[mi], &bh[ni*2]);
                mma16816(acc[mi][ni], ah[mi], &bl[ni*2]);
                mma16816(acc[mi][ni], al[mi], &bh[ni*2]);
            }
    }

    float2 bias[4];
#pragma unroll
    for (int ni = 0; ni < 4; ni++) {
        int col = n0 + wn*32 + ni*8 + (lane & 3)*2;
        bias[ni].x = bsens[col] + brec[col];
        bias[ni].y = bsens[col+1] + brec[col+1];
    }
#pragma unroll
    for (int mi = 0; mi < 2; mi++)
#pragma unroll
        for (int ni = 0; ni < 4; ni++)
#pragma unroll
            for (int e = 0; e < 2; e++) {
                int row = m0 + wm*32 + mi*16 + (lane >> 2) + e*8;
                int col = n0 + wn*32 + ni*8 + (lane & 3)*2;
                long long g = (long long)row*NH + col;
                float2 nz = *(const float2*)(noise + g);
                float2 o;
                o.x = acc[mi][ni][e*2+0] + bias[ni].x + nz.x;
                o.y = acc[mi][ni][e*2+1] + bias[ni].y + nz.y;
                *(float2*)(g_pre + g) = o;
            }
}

// ======================= krnn: persistent recurrence =======================
// EXACT R12/R15 structure (best known). Fast softplus epilogue.
#define NCTA    128
#define STG_PITCH 272
#define SM_HHI  0
#define SM_HLO  8704
#define SM_WLO  17408
#define SM_BUF  34816
#define SM_WHIP (2*SM_BUF)                   // 69632
#define WHI_PITCH 2064
#define RNN_SMEM (SM_WHIP + 64*WHI_PITCH)    // 201728
#define RED_PITCH 68
#define RED_SZ (32*RED_PITCH*4)              // 8704 B per k-group

__device__ __forceinline__ void load_pair(uint32_t bufb,
    const __nv_bfloat16* __restrict__ hhi,
    const __nv_bfloat16* __restrict__ hlo,
    int m0, int n0, int kc, int kg, int l64)
{
#pragma unroll
    for (int j = 0; j < 2; j++) {
        int i  = j*64 + l64;           // 0..127
        int r  = i >> 2;               // 0..31
        int cb = i & 3;                // 16B unit
        long long g = (long long)(m0 + r)*NH + kc + kg*32 + cb*8;
        uint32_t d = bufb + r*STG_PITCH + kg*64 + cb*16;
        cp_async16(d + SM_HHI, hhi + g);
        cp_async16(d + SM_HLO, hlo + g);
    }
#pragma unroll
    for (int j = 0; j < 4; j++) {
        int i  = j*64 + l64;           // 0..255
        int r  = i >> 2;               // 0..63
        int cb = i & 3;
        cp_async16(bufb + SM_WLO + r*STG_PITCH + kg*64 + cb*16,
                   g_Wlo + (long long)(n0 + r)*NH + kc + kg*32 + cb*8);
    }
}

__global__ void __launch_bounds__(256, 1) krnn()
{
    extern __shared__ __align__(128) char smraw[];
    const uint32_t sb  = smem_u32(smraw);
    const int tid   = threadIdx.x;
    const int wid   = tid >> 5;
    const int lane  = tid & 31;
    const int kg    = wid >> 1;
    const int slot  = wid & 1;
    const int l64   = tid & 63;
    const int mblk  = blockIdx.x >> 4;
    const int ntile = blockIdx.x & 15;
    const int m0    = mblk * 32;
    const int n0    = ntile * 64;

#pragma unroll 1
    for (int i = 0; i < 32; i++) {
        int v  = i*256 + tid;
        int r  = v >> 7;
        int ch = v & 127;
        cp_async16(sb + SM_WHIP + r*WHI_PITCH + ch*16,
                   g_Whi + (long long)(n0 + r)*NH + ch*8);
    }
    cp_commit();
    cp_wait<0>();
    __syncthreads();

    const int aRowOff = (lane & 15)*STG_PITCH;
    const int aK16    = ((lane >> 4) & 1)*16;
    const int bR16    = ((lane >> 4) & 1)*8 + (lane & 7);
    const int bK16    = ((lane >> 3) & 1)*16;
    const int kgo     = kg*64;

    const int er = tid >> 3;
    const int ec = (tid & 7)*8;
    const long long ebase = (long long)(m0 + er)*NH + n0 + ec;

    unsigned* const mybar = &g_rowbar[mblk*32];

    float hp[8];
#pragma unroll
    for (int i = 0; i < 8; i++) hp[i] = 0.f;

    float4 pr0, pr1;
    {
        const float* pp = g_pre + ebase;
        asm volatile("ld.global.nc.v4.f32 {%0,%1,%2,%3}, [%4];"
            : "=f"(pr0.x),"=f"(pr0.y),"=f"(pr0.z),"=f"(pr0.w) : "l"(pp));
        asm volatile("ld.global.nc.v4.f32 {%0,%1,%2,%3}, [%4];"
            : "=f"(pr1.x),"=f"(pr1.y),"=f"(pr1.z),"=f"(pr1.w) : "l"(pp + 4));
    }

#pragma unroll 1
    for (int t = 0; t < T_STEPS; t++) {
        float s[8];
#pragma unroll
        for (int i = 0; i < 8; i++) s[i] = 0.f;

        if (t > 0) {
            const __nv_bfloat16* __restrict__ hhi = g_hhi_all + (long long)(t-1)*BH;
            const __nv_bfloat16* __restrict__ hlo = g_hlo_all + (long long)(t-1)*BH;

            float acc[2][4][4];
#pragma unroll
            for (int a = 0; a < 2; a++)
#pragma unroll
                for (int b = 0; b < 4; b++)
#pragma unroll
                    for (int e = 0; e < 4; e++) acc[a][b][e] = 0.f;

            load_pair(sb, hhi, hlo, m0, n0, 0, kg, l64);
            cp_commit();

#pragma unroll 1
            for (int c = 0; c < 8; c++) {
                cp_wait<0>();
                pair_bar(kg);
                const uint32_t bb = sb + (c & 1)*SM_BUF;

                uint32_t ah[2][2][4], al[2][2][4], bh[2][2][4], bl[2][2][4];
#pragma unroll
                for (int sub = 0; sub < 2; sub++) {
                    const int ko = kgo + sub*32;
#pragma unroll
                    for (int mi = 0; mi < 2; mi++) {
                        uint32_t ar = mi*(16*STG_PITCH) + aRowOff + ko + aK16;
                        ldmat4(ah[sub][mi][0], ah[sub][mi][1],
                               ah[sub][mi][2], ah[sub][mi][3],
                               bb + SM_HHI + ar);
                        ldmat4(al[sub][mi][0], al[sub][mi][1],
                               al[sub][mi][2], al[sub][mi][3],
                               bb + SM_HLO + ar);
                    }
#pragma unroll
                    for (int j = 0; j < 2; j++) {
                        int brow = slot*32 + j*16 + bR16;
                        ldmat4(bh[sub][j][0], bh[sub][j][1],
                               bh[sub][j][2], bh[sub][j][3],
                               sb + SM_WHIP + brow*WHI_PITCH
                                  + c*256 + ko + bK16);
                        ldmat4(bl[sub][j][0], bl[sub][j][1],
                               bl[sub][j][2], bl[sub][j][3],
                               bb + SM_WLO + brow*STG_PITCH + ko + bK16);
                    }
                }

                if (c < 7) {
                    load_pair(sb + ((c + 1) & 1)*SM_BUF, hhi, hlo,
                              m0, n0, (c + 1)*128, kg, l64);
                    cp_commit();
                }

#pragma unroll
                for (int sub = 0; sub < 2; sub++)
#pragma unroll
                    for (int mi = 0; mi < 2; mi++)
#pragma unroll
                        for (int ni = 0; ni < 4; ni++) {
                            const uint32_t* bhp = &bh[sub][ni >> 1][(ni & 1)*2];
                            const uint32_t* blp = &bl[sub][ni >> 1][(ni & 1)*2];
                            mma16816(acc[mi][ni], ah[sub][mi], bhp);
                            mma16816(acc[mi][ni], ah[sub][mi], blp);
                            mma16816(acc[mi][ni], al[sub][mi], bhp);
                        }
            }

            __syncthreads();
            float* myred = (float*)(smraw + kg*RED_SZ);
#pragma unroll
            for (int mi = 0; mi < 2; mi++)
#pragma unroll
                for (int ni = 0; ni < 4; ni++) {
                    int r = mi*16 + (lane >> 2);
                    int ccol = slot*32 + ni*8 + (lane & 3)*2;
                    *(float2*)&myred[r*RED_PITCH + ccol] =
                        make_float2(acc[mi][ni][0], acc[mi][ni][1]);
                    *(float2*)&myred[(r + 8)*RED_PITCH + ccol] =
                        make_float2(acc[mi][ni][2], acc[mi][ni][3]);
                }
            __syncthreads();
#pragma unroll
            for (int g = 0; g < 4; g++) {
                const float* rp = (const float*)(smraw + g*RED_SZ)
                                + er*RED_PITCH + ec;
                float4 u = *(const float4*)rp;
                float4 w = *(const float4*)(rp + 4);
                s[0] += u.x; s[1] += u.y; s[2] += u.z; s[3] += u.w;
                s[4] += w.x; s[5] += w.y; s[6] += w.z; s[7] += w.w;
            }
        }

        s[0] += pr0.x; s[1] += pr0.y; s[2] += pr0.z; s[3] += pr0.w;
        s[4] += pr1.x; s[5] += pr1.y; s[6] += pr1.z; s[7] += pr1.w;

        float h[8];
#pragma unroll
        for (int i = 0; i < 8; i++) {
            float sp = fmaxf(s[i], 0.f)
                     + __logf(1.f + __expf(-fabsf(s[i])));
            h[i] = 0.2f*sp + 0.8f*hp[i];
            hp[i] = h[i];
        }
        uint32_t hiw[4], low[4];
#pragma unroll
        for (int i = 0; i < 4; i++) {
            __nv_bfloat16 a = __float2bfloat16(h[2*i]);
            __nv_bfloat16 b = __float2bfloat16(h[2*i+1]);
            hiw[i] = ((uint32_t)__bfloat16_as_ushort(b) << 16)
                   | __bfloat16_as_ushort(a);
            __nv_bfloat16 la = __float2bfloat16(h[2*i]   - __bfloat162float(a));
            __nv_bfloat16 lb = __float2bfloat16(h[2*i+1] - __bfloat162float(b));
            low[i] = ((uint32_t)__bfloat16_as_ushort(lb) << 16)
                   | __bfloat16_as_ushort(la);
        }
        long long gb = (long long)t*BH + ebase;
        *(uint4*)(g_hhi_all + gb) = make_uint4(hiw[0], hiw[1], hiw[2], hiw[3]);
        *(uint4*)(g_hlo_all + gb) = make_uint4(low[0], low[1], low[2], low[3]);

        if (t < T_STEPS - 1) {
            {
                const float* pp = g_pre + (long long)(t+1)*BH + ebase;
                asm volatile("ld.global.nc.v4.f32 {%0,%1,%2,%3}, [%4];"
                    : "=f"(pr0.x),"=f"(pr0.y),"=f"(pr0.z),"=f"(pr0.w) : "l"(pp));
                asm volatile("ld.global.nc.v4.f32 {%0,%1,%2,%3}, [%4];"
                    : "=f"(pr1.x),"=f"(pr1.y),"=f"(pr1.z),"=f"(pr1.w) : "l"(pp + 4));
            }
            __syncthreads();
            if (tid == 0) {
                __threadfence();
                atomicAdd(mybar, 1u);
                const unsigned target = (unsigned)(t + 1) * 16u;
                unsigned v;
                do {
                    asm volatile("ld.acquire.gpu.u32 %0, [%1];"
                                 : "=r"(v) : "l"(mybar));
                    if (v < target) __nanosleep(32);
                } while (v < target);
            }
            __syncthreads();
        }
    }
}

// ======================= kfinal: output projection (HMMA) ==================
// 2-stage pipeline (101 KB smem -> 2 CTAs/SM, doubles DRAM MLP).
#define F_AHI 0
#define F_ALO 18432
#define F_WH  36864
#define F_WL  43776
#define F_STG 50688
#define F_SMEM (2*F_STG)   // 101376
#define BKC   64

__device__ __forceinline__ void loadf(uint32_t bufb, int m0, int kc, int tid)
{
#pragma unroll
    for (int i = 0; i < 4; i++) {
        int v  = i*256 + tid;
        int r  = v >> 3;
        int ch = v & 7;
        long long gidx = (long long)(m0 + r)*NH + kc + ch*8;
        cp_async16(bufb + F_AHI + r*144 + ch*16, g_hhi_all + gidx);
        cp_async16(bufb + F_ALO + r*144 + ch*16, g_hlo_all + gidx);
    }
#pragma unroll
    for (int i = 0; i < 2; i++) {
        int v = i*256 + tid;
        if (v < 384) {
            int r  = v >> 3;
            int ch = v & 7;
            long long gidx = (long long)r*NH + kc + ch*8;
            cp_async16(bufb + F_WH + r*144 + ch*16, g_wouthi + gidx);
            cp_async16(bufb + F_WL + r*144 + ch*16, g_woutlo + gidx);
        }
    }
}

__global__ void __launch_bounds__(256, 2) kfinal(const float* __restrict__ bout,
                                                 float* __restrict__ out)
{
    extern __shared__ __align__(128) char smraw[];
    const uint32_t sb  = smem_u32(smraw);
    const int tid  = threadIdx.x;
    const int wid  = tid >> 5;
    const int lane = tid & 31;
    const int m0   = blockIdx.x * 128;

    const int aRow  = wid*16 + (lane & 15);
    const int aKoff = ((lane >> 4) & 1) * 16;
    const int bRow  = ((lane >> 4) & 1)*8 + (lane & 7);
    const int bKoff = ((lane >> 3) & 1) * 16;

    float acc[6][4];
#pragma unroll
    for (int n = 0; n < 6; n++)
#pragma unroll
        for (int e = 0; e < 4; e++) acc[n][e] = 0.f;

    // prologue: chunk 0 -> buf 0
    loadf(sb, m0, 0, tid);
    cp_commit();

#pragma unroll 1
    for (int c = 0; c < 16; c++) {
        cp_wait<0>();
        __syncthreads();
        const uint32_t bb = sb + (c & 1)*F_STG;

        // LDSM whole chunk first (R12-proven ordering)
        uint32_t ah[4][4], al[4][4], bh[4][3][4], bl[4][3][4];
#pragma unroll
        for (int q = 0; q < 4; q++) {
            uint32_t ar = aRow*144 + q*32 + aKoff;
            ldmat4(ah[q][0], ah[q][1], ah[q][2], ah[q][3], bb + F_AHI + ar);
            ldmat4(al[q][0], al[q][1], al[q][2], al[q][3], bb + F_ALO + ar);
#pragma unroll
            for (int j = 0; j < 3; j++) {
                uint32_t br = (bRow + j*16)*144 + q*32 + bKoff;
                ldmat4(bh[q][j][0], bh[q][j][1], bh[q][j][2], bh[q][j][3],
                       bb + F_WH + br);
                ldmat4(bl[q][j][0], bl[q][j][1], bl[q][j][2], bl[q][j][3],
                       bb + F_WL + br);
            }
        }

        // issue next chunk's loads into the other buffer (consumed at c-1)
        if (c < 15) {
            loadf(sb + ((c + 1) & 1)*F_STG, m0, (c + 1)*BKC, tid);
            cp_commit();
        }

        // MMA
#pragma unroll
        for (int q = 0; q < 4; q++)
#pragma unroll
            for (int ni = 0; ni < 6; ni++) {
                const uint32_t* bhp = &bh[q][ni >> 1][(ni & 1)*2];
                const uint32_t* blp = &bl[q][ni >> 1][(ni & 1)*2];
                mma16816(acc[ni], ah[q], bhp);
                mma16816(acc[ni], ah[q], blp);
                mma16816(acc[ni], al[q], bhp);
            }
    }

#pragma unroll
    for (int ni = 0; ni < 5; ni++)
#pragma unroll
        for (int e = 0; e < 2; e++) {
            int row = m0 + wid*16 + (lane >> 2) + e*8;
            int o   = ni*8 + (lane & 3)*2;
            if (o < NOUT)
                out[(long long)row*NOUT + o] = acc[ni][e*2+0] + bout[o];
            if (o + 1 < NOUT)
                out[(long long)row*NOUT + o + 1] = acc[ni][e*2+1] + bout[o+1];
        }
}

// ======================= launch ============================================
extern "C" void kernel_launch(void* const* d_in, const int* in_sizes, int n_in,
                              void* d_out, int out_size)
{
    const float* x     = (const float*)d_in[0];
    const float* noise = (const float*)d_in[1];
    const float* Wsens = (const float*)d_in[2];
    const float* bsens = (const float*)d_in[3];
    const float* Wrule = (const float*)d_in[4];
    const float* Wrec  = (const float*)d_in[5];
    const float* brec  = (const float*)d_in[6];
    const float* Wout  = (const float*)d_in[7];
    const float* bout  = (const float*)d_in[8];
    float* out = (float*)d_out;

    cudaFuncSetAttribute(kernelA, cudaFuncAttributeMaxDynamicSharedMemorySize,
                         A_SMEM);
    cudaFuncSetAttribute(krnn, cudaFuncAttributeMaxDynamicSharedMemorySize,
                         RNN_SMEM);
    cudaFuncSetAttribute(kfinal, cudaFuncAttributeMaxDynamicSharedMemorySize,
                         F_SMEM);

    kprepall<<<(TBROWS*KPAD)/256, 256>>>(x, Wsens, Wrule, Wout, Wrec);

    kernelA<<<dim3(16, 512), 256, A_SMEM>>>(noise, bsens, brec);
    krnn<<<NCTA, 256, RNN_SMEM>>>();
    kfinal<<<TBROWS/128, 256, F_SMEM>>>(bout, out);
}

// round 17
// speedup vs baseline: 1.0231x; 1.0231x over previous
#include <cuda_runtime.h>
#include <cuda_bf16.h>
#include <math.h>
#include <stdint.h>

// Problem constants
#define T_STEPS 256
#define BATCH   256
#define NH      1024
#define KIN     105
#define KPAD    112
#define RS      85
#define NRULE   20
#define NOUT    33
#define NOPAD   48
#define TBROWS  (T_STEPS*BATCH)   // 65536
#define BH      (BATCH*NH)        // 262144

// ---------------- scratch (static device allocations only) ----------------
__device__ float g_pre[(long long)TBROWS*NH];             // 256 MB
__device__ __nv_bfloat16 g_hhi_all[(long long)TBROWS*NH]; // 128 MB
__device__ __nv_bfloat16 g_hlo_all[(long long)TBROWS*NH]; // 128 MB
__device__ __nv_bfloat16 g_Whi[NH*NH];
__device__ __nv_bfloat16 g_Wlo[NH*NH];
__device__ __nv_bfloat16 g_xhi[(long long)TBROWS*KPAD];
__device__ __nv_bfloat16 g_xlo[(long long)TBROWS*KPAD];
__device__ __nv_bfloat16 g_Wchi[NH*KPAD];
__device__ __nv_bfloat16 g_Wclo[NH*KPAD];
__device__ __nv_bfloat16 g_wouthi[NOPAD*NH];
__device__ __nv_bfloat16 g_woutlo[NOPAD*NH];
// one barrier counter per m-row (8 chains), 128B apart
__device__ __align__(128) unsigned g_rowbar[8*32];

// ======================= helpers ===========================================
__device__ __forceinline__ uint32_t smem_u32(const void* p) {
    uint32_t a;
    asm("{ .reg .u64 t; cvta.to.shared.u64 t, %1; cvt.u32.u64 %0, t; }"
        : "=r"(a) : "l"(p));
    return a;
}
__device__ __forceinline__ void cp_async16(uint32_t dst, const void* src) {
    asm volatile("cp.async.cg.shared.global [%0], [%1], 16;"
                 :: "r"(dst), "l"(src) : "memory");
}
__device__ __forceinline__ void cp_commit() {
    asm volatile("cp.async.commit_group;" ::: "memory");
}
template<int N> __device__ __forceinline__ void cp_wait() {
    asm volatile("cp.async.wait_group %0;" :: "n"(N) : "memory");
}
__device__ __forceinline__ void ldmat4(uint32_t& r0, uint32_t& r1,
                                       uint32_t& r2, uint32_t& r3, uint32_t a) {
    asm volatile("ldmatrix.sync.aligned.m8n8.x4.shared.b16 {%0,%1,%2,%3}, [%4];"
                 : "=r"(r0), "=r"(r1), "=r"(r2), "=r"(r3) : "r"(a));
}
__device__ __forceinline__ void mma16816(float* c, const uint32_t* a,
                                         const uint32_t* b) {
    asm volatile(
        "mma.sync.aligned.m16n8k16.row.col.f32.bf16.bf16.f32 "
        "{%0,%1,%2,%3}, {%4,%5,%6,%7}, {%8,%9}, {%0,%1,%2,%3};"
        : "+f"(c[0]), "+f"(c[1]), "+f"(c[2]), "+f"(c[3])
        : "r"(a[0]), "r"(a[1]), "r"(a[2]), "r"(a[3]), "r"(b[0]), "r"(b[1]));
}
__device__ __forceinline__ void pair_bar(int kg) {
    asm volatile("bar.sync %0, 64;" :: "r"(1 + kg) : "memory");
}

// ======================= merged split/prep kernel ==========================
__global__ void kprepall(const float* __restrict__ x,
                         const float* __restrict__ Wsens,
                         const float* __restrict__ Wrule,
                         const float* __restrict__ Wout,
                         const float* __restrict__ Wrec)
{
    long long idx = (long long)blockIdx.x * 256 + threadIdx.x;

    {
        int row = (int)(idx / KPAD);
        int k   = (int)(idx - (long long)row*KPAD);
        float v = (k < KIN) ? x[(long long)row*KIN + k] : 0.f;
        __nv_bfloat16 hi = __float2bfloat16(v);
        g_xhi[idx] = hi;
        g_xlo[idx] = __float2bfloat16(v - __bfloat162float(hi));
    }
    if (idx < (long long)NH*NH) {
        float w = Wrec[idx];
        __nv_bfloat16 hi = __float2bfloat16(w);
        g_Whi[idx] = hi;
        g_Wlo[idx] = __float2bfloat16(w - __bfloat162float(hi));
    }
    if (idx < (long long)NH*KPAD) {
        int n = (int)(idx / KPAD);
        int k = (int)(idx - (long long)n*KPAD);
        float v = (k < RS) ? Wsens[n*RS + k]
                : (k < KIN) ? Wrule[n*NRULE + (k - RS)] : 0.f;
        __nv_bfloat16 hi = __float2bfloat16(v);
        g_Wchi[idx] = hi;
        g_Wclo[idx] = __float2bfloat16(v - __bfloat162float(hi));
    }
    if (idx < (long long)NOPAD*NH) {
        int o = (int)(idx / NH);
        int k = (int)(idx - (long long)o*NH);
        float v = (o < NOUT) ? Wout[o*NH + k] : 0.f;
        __nv_bfloat16 hi = __float2bfloat16(v);
        g_wouthi[idx] = hi;
        g_woutlo[idx] = __float2bfloat16(v - __bfloat162float(hi));
    }
    if (idx < 8*32) g_rowbar[idx] = 0;
}

// ======================= kernelA: pre-activations (HMMA) ===================
#define A_PITCH 240
#define A_XHI 0
#define A_XLO 30720
#define A_WCH 61440
#define A_WCL 76800
#define A_SMEM 92160

__global__ void __launch_bounds__(256) kernelA(const float* __restrict__ noise,
                                               const float* __restrict__ bsens,
                                               const float* __restrict__ brec)
{
    extern __shared__ __align__(128) char smraw[];
    const uint32_t sb = smem_u32(smraw);
    const int tid  = threadIdx.x;
    const int wid  = tid >> 5;
    const int lane = tid & 31;
    const int wm   = wid & 3;
    const int wn   = wid >> 2;
    const int m0   = blockIdx.y * 128;
    const int n0   = blockIdx.x * 64;

#pragma unroll
    for (int i = 0; i < 7; i++) {
        int v = i*256 + tid;
        int r = v / 14, ch = v - r*14;
        long long gsrc = (long long)(m0 + r)*KPAD + ch*8;
        cp_async16(sb + A_XHI + r*A_PITCH + ch*16, g_xhi + gsrc);
        cp_async16(sb + A_XLO + r*A_PITCH + ch*16, g_xlo + gsrc);
    }
#pragma unroll
    for (int i = 0; i < 4; i++) {
        int v = i*256 + tid;
        if (v < 896) {
            int r = v / 14, ch = v - r*14;
            long long gsrc = (long long)(n0 + r)*KPAD + ch*8;
            cp_async16(sb + A_WCH + r*A_PITCH + ch*16, g_Wchi + gsrc);
            cp_async16(sb + A_WCL + r*A_PITCH + ch*16, g_Wclo + gsrc);
        }
    }
    cp_commit();
    cp_wait<0>();
    __syncthreads();

    const int aKoff = ((lane >> 4) & 1) * 16;
    const int bRow  = wn*32 + ((lane >> 4) & 1)*8 + (lane & 7);
    const int bKoff = ((lane >> 3) & 1) * 16;

    float acc[2][4][4];
#pragma unroll
    for (int a = 0; a < 2; a++)
#pragma unroll
        for (int b = 0; b < 4; b++)
#pragma unroll
            for (int e = 0; e < 4; e++) acc[a][b][e] = 0.f;

#pragma unroll
    for (int k = 0; k < 7; k++) {
        uint32_t ah[2][4], al[2][4], bh[8], bl[8];
#pragma unroll
        for (int mi = 0; mi < 2; mi++) {
            uint32_t ar = (wm*32 + mi*16 + (lane & 15))*A_PITCH + k*32 + aKoff;
            ldmat4(ah[mi][0], ah[mi][1], ah[mi][2], ah[mi][3], sb + A_XHI + ar);
            ldmat4(al[mi][0], al[mi][1], al[mi][2], al[mi][3], sb + A_XLO + ar);
        }
        uint32_t br0 = bRow*A_PITCH + k*32 + bKoff;
        uint32_t br1 = (bRow + 16)*A_PITCH + k*32 + bKoff;
        ldmat4(bh[0], bh[1], bh[2], bh[3], sb + A_WCH + br0);
        ldmat4(bh[4], bh[5], bh[6], bh[7], sb + A_WCH + br1);
        ldmat4(bl[0], bl[1], bl[2], bl[3], sb + A_WCL + br0);
        ldmat4(bl[4], bl[5], bl[6], bl[7], sb + A_WCL + br1);
#pragma unroll
        for (int mi = 0; mi < 2; mi++)
#pragma unroll
            for (int ni = 0; ni < 4; ni++) {
                mma16816(acc[mi][ni], ah[mi], &bh[ni*2]);
                mma16816(acc[mi][ni], ah[mi], &bl[ni*2]);
                mma16816(acc[mi][ni], al[mi], &bh[ni*2]);
            }
    }

    float2 bias[4];
#pragma unroll
    for (int ni = 0; ni < 4; ni++) {
        int col = n0 + wn*32 + ni*8 + (lane & 3)*2;
        bias[ni].x = bsens[col] + brec[col];
        bias[ni].y = bsens[col+1] + brec[col+1];
    }
#pragma unroll
    for (int mi = 0; mi < 2; mi++)
#pragma unroll
        for (int ni = 0; ni < 4; ni++)
#pragma unroll
            for (int e = 0; e < 2; e++) {
                int row = m0 + wm*32 + mi*16 + (lane >> 2) + e*8;
                int col = n0 + wn*32 + ni*8 + (lane & 3)*2;
                long long g = (long long)row*NH + col;
                float2 nz = *(const float2*)(noise + g);
                float2 o;
                o.x = acc[mi][ni][e*2+0] + bias[ni].x + nz.x;
                o.y = acc[mi][ni][e*2+1] + bias[ni].y + nz.y;
                *(float2*)(g_pre + g) = o;
            }
}

// ======================= krnn: persistent recurrence =======================
// EXACT R12/R15 structure (best known). Fast softplus epilogue.
#define NCTA    128
#define STG_PITCH 272
#define SM_HHI  0
#define SM_HLO  8704
#define SM_WLO  17408
#define SM_BUF  34816
#define SM_WHIP (2*SM_BUF)                   // 69632
#define WHI_PITCH 2064
#define RNN_SMEM (SM_WHIP + 64*WHI_PITCH)    // 201728
#define RED_PITCH 68
#define RED_SZ (32*RED_PITCH*4)              // 8704 B per k-group

__device__ __forceinline__ void load_pair(uint32_t bufb,
    const __nv_bfloat16* __restrict__ hhi,
    const __nv_bfloat16* __restrict__ hlo,
    int m0, int n0, int kc, int kg, int l64)
{
#pragma unroll
    for (int j = 0; j < 2; j++) {
        int i  = j*64 + l64;           // 0..127
        int r  = i >> 2;               // 0..31
        int cb = i & 3;                // 16B unit
        long long g = (long long)(m0 + r)*NH + kc + kg*32 + cb*8;
        uint32_t d = bufb + r*STG_PITCH + kg*64 + cb*16;
        cp_async16(d + SM_HHI, hhi + g);
        cp_async16(d + SM_HLO, hlo + g);
    }
#pragma unroll
    for (int j = 0; j < 4; j++) {
        int i  = j*64 + l64;           // 0..255
        int r  = i >> 2;               // 0..63
        int cb = i & 3;
        cp_async16(bufb + SM_WLO + r*STG_PITCH + kg*64 + cb*16,
                   g_Wlo + (long long)(n0 + r)*NH + kc + kg*32 + cb*8);
    }
}

__global__ void __launch_bounds__(256, 1) krnn()
{
    extern __shared__ __align__(128) char smraw[];
    const uint32_t sb  = smem_u32(smraw);
    const int tid   = threadIdx.x;
    const int wid   = tid >> 5;
    const int lane  = tid & 31;
    const int kg    = wid >> 1;
    const int slot  = wid & 1;
    const int l64   = tid & 63;
    const int mblk  = blockIdx.x >> 4;
    const int ntile = blockIdx.x & 15;
    const int m0    = mblk * 32;
    const int n0    = ntile * 64;

#pragma unroll 1
    for (int i = 0; i < 32; i++) {
        int v  = i*256 + tid;
        int r  = v >> 7;
        int ch = v & 127;
        cp_async16(sb + SM_WHIP + r*WHI_PITCH + ch*16,
                   g_Whi + (long long)(n0 + r)*NH + ch*8);
    }
    cp_commit();
    cp_wait<0>();
    __syncthreads();

    const int aRowOff = (lane & 15)*STG_PITCH;
    const int aK16    = ((lane >> 4) & 1)*16;
    const int bR16    = ((lane >> 4) & 1)*8 + (lane & 7);
    const int bK16    = ((lane >> 3) & 1)*16;
    const int kgo     = kg*64;

    const int er = tid >> 3;
    const int ec = (tid & 7)*8;
    const long long ebase = (long long)(m0 + er)*NH + n0 + ec;

    unsigned* const mybar = &g_rowbar[mblk*32];

    float hp[8];
#pragma unroll
    for (int i = 0; i < 8; i++) hp[i] = 0.f;

    float4 pr0, pr1;
    {
        const float* pp = g_pre + ebase;
        asm volatile("ld.global.nc.v4.f32 {%0,%1,%2,%3}, [%4];"
            : "=f"(pr0.x),"=f"(pr0.y),"=f"(pr0.z),"=f"(pr0.w) : "l"(pp));
        asm volatile("ld.global.nc.v4.f32 {%0,%1,%2,%3}, [%4];"
            : "=f"(pr1.x),"=f"(pr1.y),"=f"(pr1.z),"=f"(pr1.w) : "l"(pp + 4));
    }

#pragma unroll 1
    for (int t = 0; t < T_STEPS; t++) {
        float s[8];
#pragma unroll
        for (int i = 0; i < 8; i++) s[i] = 0.f;

        if (t > 0) {
            const __nv_bfloat16* __restrict__ hhi = g_hhi_all + (long long)(t-1)*BH;
            const __nv_bfloat16* __restrict__ hlo = g_hlo_all + (long long)(t-1)*BH;

            float acc[2][4][4];
#pragma unroll
            for (int a = 0; a < 2; a++)
#pragma unroll
                for (int b = 0; b < 4; b++)
#pragma unroll
                    for (int e = 0; e < 4; e++) acc[a][b][e] = 0.f;

            load_pair(sb, hhi, hlo, m0, n0, 0, kg, l64);
            cp_commit();

#pragma unroll 1
            for (int c = 0; c < 8; c++) {
                cp_wait<0>();
                pair_bar(kg);
                const uint32_t bb = sb + (c & 1)*SM_BUF;

                uint32_t ah[2][2][4], al[2][2][4], bh[2][2][4], bl[2][2][4];
#pragma unroll
                for (int sub = 0; sub < 2; sub++) {
                    const int ko = kgo + sub*32;
#pragma unroll
                    for (int mi = 0; mi < 2; mi++) {
                        uint32_t ar = mi*(16*STG_PITCH) + aRowOff + ko + aK16;
                        ldmat4(ah[sub][mi][0], ah[sub][mi][1],
                               ah[sub][mi][2], ah[sub][mi][3],
                               bb + SM_HHI + ar);
                        ldmat4(al[sub][mi][0], al[sub][mi][1],
                               al[sub][mi][2], al[sub][mi][3],
                               bb + SM_HLO + ar);
                    }
#pragma unroll
                    for (int j = 0; j < 2; j++) {
                        int brow = slot*32 + j*16 + bR16;
                        ldmat4(bh[sub][j][0], bh[sub][j][1],
                               bh[sub][j][2], bh[sub][j][3],
                               sb + SM_WHIP + brow*WHI_PITCH
                                  + c*256 + ko + bK16);
                        ldmat4(bl[sub][j][0], bl[sub][j][1],
                               bl[sub][j][2], bl[sub][j][3],
                               bb + SM_WLO + brow*STG_PITCH + ko + bK16);
                    }
                }

                if (c < 7) {
                    load_pair(sb + ((c + 1) & 1)*SM_BUF, hhi, hlo,
                              m0, n0, (c + 1)*128, kg, l64);
                    cp_commit();
                }

#pragma unroll
                for (int sub = 0; sub < 2; sub++)
#pragma unroll
                    for (int mi = 0; mi < 2; mi++)
#pragma unroll
                        for (int ni = 0; ni < 4; ni++) {
                            const uint32_t* bhp = &bh[sub][ni >> 1][(ni & 1)*2];
                            const uint32_t* blp = &bl[sub][ni >> 1][(ni & 1)*2];
                            mma16816(acc[mi][ni], ah[sub][mi], bhp);
                            mma16816(acc[mi][ni], ah[sub][mi], blp);
                            mma16816(acc[mi][ni], al[sub][mi], bhp);
                        }
            }

            __syncthreads();
            float* myred = (float*)(smraw + kg*RED_SZ);
#pragma unroll
            for (int mi = 0; mi < 2; mi++)
#pragma unroll
                for (int ni = 0; ni < 4; ni++) {
                    int r = mi*16 + (lane >> 2);
                    int ccol = slot*32 + ni*8 + (lane & 3)*2;
                    *(float2*)&myred[r*RED_PITCH + ccol] =
                        make_float2(acc[mi][ni][0], acc[mi][ni][1]);
                    *(float2*)&myred[(r + 8)*RED_PITCH + ccol] =
                        make_float2(acc[mi][ni][2], acc[mi][ni][3]);
                }
            __syncthreads();
#pragma unroll
            for (int g = 0; g < 4; g++) {
                const float* rp = (const float*)(smraw + g*RED_SZ)
                                + er*RED_PITCH + ec;
                float4 u = *(const float4*)rp;
                float4 w = *(const float4*)(rp + 4);
                s[0] += u.x; s[1] += u.y; s[2] += u.z; s[3] += u.w;
                s[4] += w.x; s[5] += w.y; s[6] += w.z; s[7] += w.w;
            }
        }

        s[0] += pr0.x; s[1] += pr0.y; s[2] += pr0.z; s[3] += pr0.w;
        s[4] += pr1.x; s[5] += pr1.y; s[6] += pr1.z; s[7] += pr1.w;

        float h[8];
#pragma unroll
        for (int i = 0; i < 8; i++) {
            float sp = fmaxf(s[i], 0.f)
                     + __logf(1.f + __expf(-fabsf(s[i])));
            h[i] = 0.2f*sp + 0.8f*hp[i];
            hp[i] = h[i];
        }
        uint32_t hiw[4], low[4];
#pragma unroll
        for (int i = 0; i < 4; i++) {
            __nv_bfloat16 a = __float2bfloat16(h[2*i]);
            __nv_bfloat16 b = __float2bfloat16(h[2*i+1]);
            hiw[i] = ((uint32_t)__bfloat16_as_ushort(b) << 16)
                   | __bfloat16_as_ushort(a);
            __nv_bfloat16 la = __float2bfloat16(h[2*i]   - __bfloat162float(a));
            __nv_bfloat16 lb = __float2bfloat16(h[2*i+1] - __bfloat162float(b));
            low[i] = ((uint32_t)__bfloat16_as_ushort(lb) << 16)
                   | __bfloat16_as_ushort(la);
        }
        long long gb = (long long)t*BH + ebase;
        *(uint4*)(g_hhi_all + gb) = make_uint4(hiw[0], hiw[1], hiw[2], hiw[3]);
        *(uint4*)(g_hlo_all + gb) = make_uint4(low[0], low[1], low[2], low[3]);

        if (t < T_STEPS - 1) {
            {
                const float* pp = g_pre + (long long)(t+1)*BH + ebase;
                asm volatile("ld.global.nc.v4.f32 {%0,%1,%2,%3}, [%4];"
                    : "=f"(pr0.x),"=f"(pr0.y),"=f"(pr0.z),"=f"(pr0.w) : "l"(pp));
                asm volatile("ld.global.nc.v4.f32 {%0,%1,%2,%3}, [%4];"
                    : "=f"(pr1.x),"=f"(pr1.y),"=f"(pr1.z),"=f"(pr1.w) : "l"(pp + 4));
            }
            __syncthreads();
            if (tid == 0) {
                __threadfence();
                atomicAdd(mybar, 1u);
                const unsigned target = (unsigned)(t + 1) * 16u;
                unsigned v;
                do {
                    asm volatile("ld.acquire.gpu.u32 %0, [%1];"
                                 : "=r"(v) : "l"(mybar));
                    if (v < target) __nanosleep(32);
                } while (v < target);
            }
            __syncthreads();
        }
    }
}

// ======================= kfinal: output projection (HMMA) ==================
// 4-stage pipeline with HALF-size chunks (K=32): F_SMEM=112640 -> 2 CTAs/SM
// AND wait<2> prefetch depth (occupancy x depth both preserved).
#define F_PITCH 80
#define F_AHI 0
#define F_ALO 10240
#define F_WH  20480
#define F_WL  24320
#define F_STG 28160
#define F_SMEM (4*F_STG)   // 112640
#define F_BKC 32
#define F_NCHUNK 32

__device__ __forceinline__ void loadf(uint32_t bufb, int m0, int kc, int tid)
{
#pragma unroll
    for (int i = 0; i < 2; i++) {      // A hi+lo: 128 rows x 4 units
        int v  = i*256 + tid;          // 0..511
        int r  = v >> 2;
        int cb = v & 3;
        long long gidx = (long long)(m0 + r)*NH + kc + cb*8;
        cp_async16(bufb + F_AHI + r*F_PITCH + cb*16, g_hhi_all + gidx);
        cp_async16(bufb + F_ALO + r*F_PITCH + cb*16, g_hlo_all + gidx);
    }
    if (tid < 192) {                   // W hi+lo: 48 rows x 4 units
        int r  = tid >> 2;
        int cb = tid & 3;
        long long gidx = (long long)r*NH + kc + cb*8;
        cp_async16(bufb + F_WH + r*F_PITCH + cb*16, g_wouthi + gidx);
        cp_async16(bufb + F_WL + r*F_PITCH + cb*16, g_woutlo + gidx);
    }
}

__global__ void __launch_bounds__(256, 2) kfinal(const float* __restrict__ bout,
                                                 float* __restrict__ out)
{
    extern __shared__ __align__(128) char smraw[];
    const uint32_t sb  = smem_u32(smraw);
    const int tid  = threadIdx.x;
    const int wid  = tid >> 5;
    const int lane = tid & 31;
    const int m0   = blockIdx.x * 128;

    const int aRow  = wid*16 + (lane & 15);
    const int aKoff = ((lane >> 4) & 1) * 16;
    const int bRow  = ((lane >> 4) & 1)*8 + (lane & 7);
    const int bKoff = ((lane >> 3) & 1) * 16;

    float acc[6][4];
#pragma unroll
    for (int n = 0; n < 6; n++)
#pragma unroll
        for (int e = 0; e < 4; e++) acc[n][e] = 0.f;

#pragma unroll
    for (int c = 0; c < 3; c++) {
        loadf(sb + c*F_STG, m0, c*F_BKC, tid);
        cp_commit();
    }
#pragma unroll 1
    for (int c = 0; c < F_NCHUNK; c++) {
        if (c < F_NCHUNK - 2)       cp_wait<2>();
        else if (c == F_NCHUNK - 2) cp_wait<1>();
        else                        cp_wait<0>();
        __syncthreads();
        if (c < F_NCHUNK - 3) {
            loadf(sb + ((c + 3) & 3)*F_STG, m0, (c + 3)*F_BKC, tid);
            cp_commit();
        }
        const uint32_t bb = sb + (c & 3)*F_STG;
#pragma unroll
        for (int q = 0; q < 2; q++) {
            uint32_t ah[4], al[4], bh[3][4], bl[3][4];
            uint32_t ar = aRow*F_PITCH + q*32 + aKoff;
            ldmat4(ah[0], ah[1], ah[2], ah[3], bb + F_AHI + ar);
            ldmat4(al[0], al[1], al[2], al[3], bb + F_ALO + ar);
#pragma unroll
            for (int j = 0; j < 3; j++) {
                uint32_t br = (bRow + j*16)*F_PITCH + q*32 + bKoff;
                ldmat4(bh[j][0], bh[j][1], bh[j][2], bh[j][3], bb + F_WH + br);
                ldmat4(bl[j][0], bl[j][1], bl[j][2], bl[j][3], bb + F_WL + br);
            }
#pragma unroll
            for (int ni = 0; ni < 6; ni++) {
                const uint32_t* bhp = &bh[ni >> 1][(ni & 1)*2];
                const uint32_t* blp = &bl[ni >> 1][(ni & 1)*2];
                mma16816(acc[ni], ah, bhp);
                mma16816(acc[ni], ah, blp);
                mma16816(acc[ni], al, bhp);
            }
        }
    }

#pragma unroll
    for (int ni = 0; ni < 5; ni++)
#pragma unroll
        for (int e = 0; e < 2; e++) {
            int row = m0 + wid*16 + (lane >> 2) + e*8;
            int o   = ni*8 + (lane & 3)*2;
            if (o < NOUT)
                out[(long long)row*NOUT + o] = acc[ni][e*2+0] + bout[o];
            if (o + 1 < NOUT)
                out[(long long)row*NOUT + o + 1] = acc[ni][e*2+1] + bout[o+1];
        }
}

// ======================= launch ============================================
extern "C" void kernel_launch(void* const* d_in, const int* in_sizes, int n_in,
                              void* d_out, int out_size)
{
    const float* x     = (const float*)d_in[0];
    const float* noise = (const float*)d_in[1];
    const float* Wsens = (const float*)d_in[2];
    const float* bsens = (const float*)d_in[3];
    const float* Wrule = (const float*)d_in[4];
    const float* Wrec  = (const float*)d_in[5];
    const float* brec  = (const float*)d_in[6];
    const float* Wout  = (const float*)d_in[7];
    const float* bout  = (const float*)d_in[8];
    float* out = (float*)d_out;

    cudaFuncSetAttribute(kernelA, cudaFuncAttributeMaxDynamicSharedMemorySize,
                         A_SMEM);
    cudaFuncSetAttribute(krnn, cudaFuncAttributeMaxDynamicSharedMemorySize,
                         RNN_SMEM);
    cudaFuncSetAttribute(kfinal, cudaFuncAttributeMaxDynamicSharedMemorySize,
                         F_SMEM);

    kprepall<<<(TBROWS*KPAD)/256, 256>>>(x, Wsens, Wrule, Wout, Wrec);

    kernelA<<<dim3(16, 512), 256, A_SMEM>>>(noise, bsens, brec);
    krnn<<<NCTA, 256, RNN_SMEM>>>();
    kfinal<<<TBROWS/128, 256, F_SMEM>>>(bout, out);
}